// round 1
// baseline (speedup 1.0000x reference)
#include <cuda_runtime.h>

#define TLEN   8192          // input/output time length per row
#define TUP    16384         // upsampled length
#define TILE   1024          // outputs per block
#define NTHR   256
#define NPAIRS (TILE + 6)    // 1030 act pairs per block (with halo)
#define NXS    (TILE + 16)   // x smem tile (need TILE+13)
#define NAS    2320          // skewed act smem: S(2059)=2316 -> pad

// skewed act index: groups of 8 floats padded by 1 -> stride-8 access conflict-free
__device__ __forceinline__ int S(int i) { return i + (i >> 3); }

__device__ __forceinline__ float snake(float up, float a, float inv_b) {
    float s = __sinf(up * a);
    return fmaf(s * s, inv_b, up);
}

// act at arbitrary (possibly out-of-range) upsampled index t, edge-clamped
__device__ __forceinline__ float act_general(int t, int m0, const float* xs,
                                             const float* uf2, float a, float inv_b) {
    t = t < 0 ? 0 : (t > TUP - 1 ? TUP - 1 : t);
    int s  = t >> 1;
    int xi = s + 3 - m0;          // xs index of x[s-3]  (xbase = m0-6)
    float up;
    if (t & 1) {
        up =      uf2[10] * xs[xi + 1];
        up = fmaf(uf2[8],   xs[xi + 2], up);
        up = fmaf(uf2[6],   xs[xi + 3], up);
        up = fmaf(uf2[4],   xs[xi + 4], up);
        up = fmaf(uf2[2],   xs[xi + 5], up);
        up = fmaf(uf2[0],   xs[xi + 6], up);
    } else {
        up =      uf2[11] * xs[xi + 0];
        up = fmaf(uf2[9],   xs[xi + 1], up);
        up = fmaf(uf2[7],   xs[xi + 2], up);
        up = fmaf(uf2[5],   xs[xi + 3], up);
        up = fmaf(uf2[3],   xs[xi + 4], up);
        up = fmaf(uf2[1],   xs[xi + 5], up);
    }
    return snake(up, a, inv_b);
}

__global__ void __launch_bounds__(NTHR)
act1d_kernel(const float* __restrict__ x,
             const float* __restrict__ upf,
             const float* __restrict__ dnf,
             const float* __restrict__ alpha,
             const float* __restrict__ beta,
             float* __restrict__ out,
             int nch)
{
    __shared__ __align__(16) float xs[NXS];
    __shared__ __align__(16) float as[NAS];

    const int tid = threadIdx.x;
    const int row = blockIdx.y;
    const int m0  = blockIdx.x * TILE;
    const int ch  = row % nch;

    const float a     = __expf(__ldg(alpha + ch));
    const float inv_b = 1.0f / (__expf(__ldg(beta + ch)) + 1e-9f);

    float uf2[12];
    #pragma unroll
    for (int i = 0; i < 12; i++) uf2[i] = 2.0f * __ldg(upf + i);

    // ---------------- phase 0: x tile (edge-clamped) ----------------
    const float* xrow = x + (size_t)row * TLEN;
    const int xbase = m0 - 6;
    for (int i = tid; i < TILE + 13; i += NTHR) {
        int g = xbase + i;
        g = g < 0 ? 0 : (g > TLEN - 1 ? TLEN - 1 : g);
        xs[i] = xrow[g];
    }
    __syncthreads();

    // ---------------- phase 1: act tile (2*TILE + halo) ----------------
    // logical act index i maps to t = tb + i; pair q -> i = 2q, 2q+1, s = m0-3+q
    const int tb = 2 * m0 - 6;
    {
        const int q0   = tid * 4;
        const int t_lo = tb + 2 * q0;
        if (t_lo >= 0 && t_lo + 7 <= TUP - 1) {
            // fast interior path: 10 x values (vector LDS), 8 acts
            float4 x03 = *(const float4*)(xs + q0);
            float4 x47 = *(const float4*)(xs + q0 + 4);
            float2 x89 = *(const float2*)(xs + q0 + 8);
            float xv[10] = {x03.x, x03.y, x03.z, x03.w,
                            x47.x, x47.y, x47.z, x47.w,
                            x89.x, x89.y};
            #pragma unroll
            for (int k = 0; k < 4; k++) {
                float ue =      uf2[11] * xv[k + 0];
                ue = fmaf(uf2[9],  xv[k + 1], ue);
                ue = fmaf(uf2[7],  xv[k + 2], ue);
                ue = fmaf(uf2[5],  xv[k + 3], ue);
                ue = fmaf(uf2[3],  xv[k + 4], ue);
                ue = fmaf(uf2[1],  xv[k + 5], ue);
                float uo =      uf2[10] * xv[k + 1];
                uo = fmaf(uf2[8],  xv[k + 2], uo);
                uo = fmaf(uf2[6],  xv[k + 3], uo);
                uo = fmaf(uf2[4],  xv[k + 4], uo);
                uo = fmaf(uf2[2],  xv[k + 5], uo);
                uo = fmaf(uf2[0],  xv[k + 6], uo);
                // skewed stores: i = 8*tid + 2k / 2k+1 -> addr 9*tid + 2k (+1)
                as[9 * tid + 2 * k]     = snake(ue, a, inv_b);
                as[9 * tid + 2 * k + 1] = snake(uo, a, inv_b);
            }
        } else {
            // edge path (only a few threads in first/last block of a row)
            #pragma unroll
            for (int k = 0; k < 4; k++) {
                int q = q0 + k;
                as[S(2 * q)]     = act_general(tb + 2 * q,     m0, xs, uf2, a, inv_b);
                as[S(2 * q + 1)] = act_general(tb + 2 * q + 1, m0, xs, uf2, a, inv_b);
            }
        }
        // tail pairs 1024..NPAIRS-1
        for (int q = NTHR * 4 + tid; q < NPAIRS; q += NTHR) {
            as[S(2 * q)]     = act_general(tb + 2 * q,     m0, xs, uf2, a, inv_b);
            as[S(2 * q + 1)] = act_general(tb + 2 * q + 1, m0, xs, uf2, a, inv_b);
        }
    }
    __syncthreads();

    // ---------------- phase 2: downsample, 4 outputs per thread ----------------
    float df[12];
    #pragma unroll
    for (int i = 0; i < 12; i++) df[i] = __ldg(dnf + i);

    // out[m], m = m0 + 4*tid + k uses logical act i = 8*tid + 1 + (2k + j)
    float A[18];
    const int base = 8 * tid + 1;
    #pragma unroll
    for (int j = 0; j < 18; j++) A[j] = as[S(base + j)];

    float4 o;
    #pragma unroll
    for (int k = 0; k < 4; k++) {
        float r = df[0] * A[2 * k];
        #pragma unroll
        for (int j = 1; j < 12; j++) r = fmaf(df[j], A[2 * k + j], r);
        ((float*)&o)[k] = r;
    }
    *(float4*)(out + (size_t)row * TLEN + m0 + 4 * tid) = o;
}

extern "C" void kernel_launch(void* const* d_in, const int* in_sizes, int n_in,
                              void* d_out, int out_size) {
    const float* x     = (const float*)d_in[0];
    const float* upf   = (const float*)d_in[1];
    const float* dnf   = (const float*)d_in[2];
    const float* alpha = (const float*)d_in[3];
    const float* beta  = (const float*)d_in[4];
    float* out = (float*)d_out;

    const int rows = in_sizes[0] / TLEN;     // B*C = 8192
    const int nch  = in_sizes[3];            // C = 512

    dim3 grid(TLEN / TILE, rows);
    act1d_kernel<<<grid, NTHR>>>(x, upf, dnf, alpha, beta, out, nch);
}

// round 2
// speedup vs baseline: 1.4390x; 1.4390x over previous
#include <cuda_runtime.h>

#define TLEN 8192          // row length (in = out)
#define TUP  16384
#define TILE 1024          // outputs per block
#define NTHR 256
#define NXS  1040          // x smem: covers [m0-8, m0+1032)
#define NEO  1032          // E/O act arrays (1030 used + float4 overread pad)

__device__ __forceinline__ float snake(float u, float a, float ib) {
    float s = __sinf(u * a);
    return fmaf(s * s, ib, u);    // u is already the doubled up-sample value
}

__global__ void __launch_bounds__(NTHR, 4)
act1d_kernel(const float* __restrict__ x,
             const float* __restrict__ upf,
             const float* __restrict__ dnf,
             const float* __restrict__ alpha,
             const float* __restrict__ beta,
             float* __restrict__ out,
             int nch)
{
    __shared__ __align__(16) float xs[NXS];
    __shared__ __align__(16) float Es[NEO];
    __shared__ __align__(16) float Os[NEO];

    const int tid = threadIdx.x;
    const int row = blockIdx.y;
    const int m0  = blockIdx.x * TILE;
    const int ch  = row % nch;

    const float a  = __expf(__ldg(alpha + ch));
    const float ib = __fdividef(1.0f, __expf(__ldg(beta + ch)) + 1e-9f);

    const float* xrow = x + (size_t)row * TLEN;
    const bool first = (m0 == 0);
    const bool last  = (m0 + TILE == TLEN);

    // ---- phase 0: xs[i] = x_clamped[m0-8+i], i in [0,1040) ----
    if (!first && !last) {
        const float4* src = (const float4*)(xrow + (m0 - 8));
        ((float4*)xs)[tid] = src[tid];
        if (tid < (NXS / 4 - NTHR))                       // 4 extra float4s
            ((float4*)xs)[NTHR + tid] = src[NTHR + tid];
    } else {
        #pragma unroll
        for (int it = 0; it < 5; it++) {
            int i = tid + it * NTHR;
            if (i < NXS) {
                int g = m0 - 8 + i;
                g = g < 0 ? 0 : (g > TLEN - 1 ? TLEN - 1 : g);
                xs[i] = xrow[g];
            }
        }
    }
    __syncthreads();

    // ---- phase 1: act pairs. pair q: s = m0-3+q ----
    //   E[q] = act[2s]   = snake( sum_r uf2[11-2r] * xs[q+2+r] )
    //   O[q] = act[2s+1] = snake( sum_r uf2[10-2r] * xs[q+3+r] )
    {
        float uf2[12];
        {
            const float4* u4 = (const float4*)upf;
            float4 u0 = __ldg(u4), u1 = __ldg(u4 + 1), u2 = __ldg(u4 + 2);
            uf2[0] = 2.f*u0.x; uf2[1] = 2.f*u0.y; uf2[2]  = 2.f*u0.z; uf2[3]  = 2.f*u0.w;
            uf2[4] = 2.f*u1.x; uf2[5] = 2.f*u1.y; uf2[6]  = 2.f*u1.z; uf2[7]  = 2.f*u1.w;
            uf2[8] = 2.f*u2.x; uf2[9] = 2.f*u2.y; uf2[10] = 2.f*u2.z; uf2[11] = 2.f*u2.w;
        }

        const int q0 = 4 * tid;
        float4 v0 = *(const float4*)(xs + q0);
        float4 v1 = *(const float4*)(xs + q0 + 4);
        float4 v2 = *(const float4*)(xs + q0 + 8);
        float xv[12] = {v0.x, v0.y, v0.z, v0.w,
                        v1.x, v1.y, v1.z, v1.w,
                        v2.x, v2.y, v2.z, v2.w};

        float ev[4], ov[4];
        #pragma unroll
        for (int k = 0; k < 4; k++) {
            float ue =      uf2[11] * xv[k + 2];
            ue = fmaf(uf2[9],  xv[k + 3], ue);
            ue = fmaf(uf2[7],  xv[k + 4], ue);
            ue = fmaf(uf2[5],  xv[k + 5], ue);
            ue = fmaf(uf2[3],  xv[k + 6], ue);
            ue = fmaf(uf2[1],  xv[k + 7], ue);
            float uo =      uf2[10] * xv[k + 3];
            uo = fmaf(uf2[8],  xv[k + 4], uo);
            uo = fmaf(uf2[6],  xv[k + 5], uo);
            uo = fmaf(uf2[4],  xv[k + 6], uo);
            uo = fmaf(uf2[2],  xv[k + 7], uo);
            uo = fmaf(uf2[0],  xv[k + 8], uo);
            ev[k] = snake(ue, a, ib);
            ov[k] = snake(uo, a, ib);
        }
        *(float4*)(Es + q0) = make_float4(ev[0], ev[1], ev[2], ev[3]);
        *(float4*)(Os + q0) = make_float4(ov[0], ov[1], ov[2], ov[3]);

        // first block: act indices t<0 clamp to act[0] == E[3] (owned by tid 0)
        if (first && tid == 0) {
            float a0v = ev[3];
            Es[0] = a0v; Es[1] = a0v; Es[2] = a0v;
            Os[0] = a0v; Os[1] = a0v; Os[2] = a0v;
        }

        // halo pairs q = 1024..1029
        if (tid < 6) {
            const int q = TILE + tid;
            const float* xq = xs + q + 2;
            float ue =      uf2[11] * xq[0];
            ue = fmaf(uf2[9],  xq[1], ue);
            ue = fmaf(uf2[7],  xq[2], ue);
            ue = fmaf(uf2[5],  xq[3], ue);
            ue = fmaf(uf2[3],  xq[4], ue);
            ue = fmaf(uf2[1],  xq[5], ue);
            float uo =      uf2[10] * xq[1];
            uo = fmaf(uf2[8],  xq[2], uo);
            uo = fmaf(uf2[6],  xq[3], uo);
            uo = fmaf(uf2[4],  xq[4], uo);
            uo = fmaf(uf2[2],  xq[5], uo);
            uo = fmaf(uf2[0],  xq[6], uo);
            float Eh = snake(ue, a, ib);
            float Oh = snake(uo, a, ib);
            if (last) {
                // t > 16383 clamps to act[16383] == O[1026] (tid==2 owns it)
                if (tid == 2) {
                    Es[q] = Eh; Os[q] = Oh;
                    Es[1027] = Oh; Es[1028] = Oh; Es[1029] = Oh;
                    Os[1027] = Oh; Os[1028] = Oh; Os[1029] = Oh;
                } else if (tid < 2) {
                    Es[q] = Eh; Os[q] = Oh;
                }
                // tid 3..5: skip (values owned by fixup above)
            } else {
                Es[q] = Eh; Os[q] = Oh;
            }
        }
    }
    __syncthreads();

    // ---- phase 2: out[m0+4tid+k] = sum_r df[2r]*O[b+k+r] + df[2r+1]*E[b+k+r+1] ----
    {
        float df[12];
        {
            const float4* d4 = (const float4*)dnf;
            float4 d0 = __ldg(d4), d1 = __ldg(d4 + 1), d2 = __ldg(d4 + 2);
            df[0] = d0.x; df[1] = d0.y; df[2]  = d0.z; df[3]  = d0.w;
            df[4] = d1.x; df[5] = d1.y; df[6]  = d1.z; df[7]  = d1.w;
            df[8] = d2.x; df[9] = d2.y; df[10] = d2.z; df[11] = d2.w;
        }

        const int b = 4 * tid;
        float4 p0 = *(const float4*)(Os + b);
        float4 p1 = *(const float4*)(Os + b + 4);
        float  o8 = Os[b + 8];
        float4 e0 = *(const float4*)(Es + b);
        float4 e1 = *(const float4*)(Es + b + 4);
        float4 e2 = *(const float4*)(Es + b + 8);

        float o[9] = {p0.x, p0.y, p0.z, p0.w, p1.x, p1.y, p1.z, p1.w, o8};
        float e[10] = {e0.x, e0.y, e0.z, e0.w, e1.x, e1.y, e1.z, e1.w, e2.x, e2.y};

        float4 r4;
        #pragma unroll
        for (int k = 0; k < 4; k++) {
            float r = df[0] * o[k];
            r = fmaf(df[1],  e[k + 1], r);
            r = fmaf(df[2],  o[k + 1], r);
            r = fmaf(df[3],  e[k + 2], r);
            r = fmaf(df[4],  o[k + 2], r);
            r = fmaf(df[5],  e[k + 3], r);
            r = fmaf(df[6],  o[k + 3], r);
            r = fmaf(df[7],  e[k + 4], r);
            r = fmaf(df[8],  o[k + 4], r);
            r = fmaf(df[9],  e[k + 5], r);
            r = fmaf(df[10], o[k + 5], r);
            r = fmaf(df[11], e[k + 6], r);
            ((float*)&r4)[k] = r;
        }
        *(float4*)(out + (size_t)row * TLEN + m0 + b) = r4;
    }
}

extern "C" void kernel_launch(void* const* d_in, const int* in_sizes, int n_in,
                              void* d_out, int out_size) {
    const float* x     = (const float*)d_in[0];
    const float* upf   = (const float*)d_in[1];
    const float* dnf   = (const float*)d_in[2];
    const float* alpha = (const float*)d_in[3];
    const float* beta  = (const float*)d_in[4];
    float* out = (float*)d_out;

    const int rows = in_sizes[0] / TLEN;   // B*C
    const int nch  = in_sizes[3];          // C

    dim3 grid(TLEN / TILE, rows);
    act1d_kernel<<<grid, NTHR>>>(x, upf, dnf, alpha, beta, out, nch);
}

// round 3
// speedup vs baseline: 1.5945x; 1.1081x over previous
#include <cuda_runtime.h>

#define TLEN 8192
#define TILE 1024
#define NTHR 256
#define NEO  1032            // 1030 act pairs used + pad

typedef unsigned long long u64;

__device__ __forceinline__ u64 pk2(float lo, float hi) {
    u64 r; asm("mov.b64 %0,{%1,%2};" : "=l"(r) : "f"(lo), "f"(hi)); return r;
}
__device__ __forceinline__ void upk2(u64 p, float& lo, float& hi) {
    asm("mov.b64 {%0,%1},%2;" : "=f"(lo), "=f"(hi) : "l"(p));
}
__device__ __forceinline__ u64 fma2(u64 a, u64 b, u64 c) {
    u64 d; asm("fma.rn.f32x2 %0,%1,%2,%3;" : "=l"(d) : "l"(a), "l"(b), "l"(c)); return d;
}
__device__ __forceinline__ u64 mul2(u64 a, u64 b) {
    u64 d; asm("mul.rn.f32x2 %0,%1,%2;" : "=l"(d) : "l"(a), "l"(b)); return d;
}

__device__ __forceinline__ float snake(float u, float a, float ib) {
    float s = __sinf(u * a);
    return fmaf(s * s, ib, u);
}

__global__ void __launch_bounds__(NTHR, 4)
act1d_kernel(const float* __restrict__ x,
             const float* __restrict__ upf,
             const float* __restrict__ dnf,
             const float* __restrict__ alpha,
             const float* __restrict__ beta,
             float* __restrict__ out,
             int nch)
{
    __shared__ __align__(16) float Es[NEO];
    __shared__ __align__(16) float Os[NEO];

    const int tid = threadIdx.x;
    const int row = blockIdx.y;
    const int m0  = blockIdx.x * TILE;
    const int ch  = row % nch;
    const int b   = 4 * tid;          // first owned pair / output

    const float a  = __expf(__ldg(alpha + ch));
    const float ib = __fdividef(1.0f, __expf(__ldg(beta + ch)) + 1e-9f);

    const float* xrow = x + (size_t)row * TLEN;
    const bool first = (m0 == 0);
    const bool last  = (m0 + TILE == TLEN);

    // ---- x values for owned pairs: xv[j] = x_clamped[m0 + b - 8 + j], j=0..11 ----
    float xv[12];
    if (!(first && tid < 32)) {                       // warp-uniform
        const float4* s = (const float4*)(xrow + (m0 + b - 8));
        float4 v0 = s[0], v1 = s[1], v2 = s[2];
        xv[0]=v0.x; xv[1]=v0.y; xv[2] =v0.z; xv[3] =v0.w;
        xv[4]=v1.x; xv[5]=v1.y; xv[6] =v1.z; xv[7] =v1.w;
        xv[8]=v2.x; xv[9]=v2.y; xv[10]=v2.z; xv[11]=v2.w;
    } else {                                          // first block, warp 0: clamp low
        const int xb = b - 8;
        #pragma unroll
        for (int j = 0; j < 12; j++) {
            int g = xb + j;
            xv[j] = xrow[g < 0 ? 0 : g];
        }
    }

    // ---- phase 1: 4 (E,O) act pairs via packed f32x2 FMA ----
    // pair q = b+k: E[q] = sum_r 2*uf[11-2r]*x[m0-6+q+r], O[q] = sum_r 2*uf[10-2r]*x[m0-5+q+r]
    float ev[4], ov[4];
    {
        u64 F[6];
        {
            const float4* u4 = (const float4*)upf;
            float4 u0 = __ldg(u4), u1 = __ldg(u4 + 1), u2 = __ldg(u4 + 2);
            F[0] = pk2(2.f*u2.w, 2.f*u2.z);   // uf[11], uf[10]
            F[1] = pk2(2.f*u2.y, 2.f*u2.x);   // uf[9],  uf[8]
            F[2] = pk2(2.f*u1.w, 2.f*u1.z);
            F[3] = pk2(2.f*u1.y, 2.f*u1.x);
            F[4] = pk2(2.f*u0.w, 2.f*u0.z);
            F[5] = pk2(2.f*u0.y, 2.f*u0.x);   // uf[1],  uf[0]
        }
        u64 P[9];                              // P[i] = (xv[i+2], xv[i+3])
        #pragma unroll
        for (int i = 0; i < 9; i++) P[i] = pk2(xv[i + 2], xv[i + 3]);

        const u64 a2  = pk2(a, a);
        const u64 ib2 = pk2(ib, ib);

        #pragma unroll
        for (int k = 0; k < 4; k++) {
            u64 u = mul2(F[0], P[k]);
            u = fma2(F[1], P[k + 1], u);
            u = fma2(F[2], P[k + 2], u);
            u = fma2(F[3], P[k + 3], u);
            u = fma2(F[4], P[k + 4], u);
            u = fma2(F[5], P[k + 5], u);
            u64 t = mul2(u, a2);
            float te, to; upk2(t, te, to);
            u64 S  = pk2(__sinf(te), __sinf(to));
            u64 r  = fma2(mul2(S, S), ib2, u);
            upk2(r, ev[k], ov[k]);
        }

        // first block, tid 0: act indices t<0 clamp to act[0] == ev[3]
        if (first && tid == 0) {
            ev[0] = ev[1] = ev[2] = ev[3];
            ov[0] = ov[1] = ov[2] = ev[3];
        }

        *(float4*)(Es + b) = make_float4(ev[0], ev[1], ev[2], ev[3]);
        *(float4*)(Os + b) = make_float4(ov[0], ov[1], ov[2], ov[3]);

        // halo pairs q = 1024..1029 (scalar, clamped global reads)
        if (tid < 6) {
            float uf2[12];
            #pragma unroll
            for (int j = 0; j < 12; j++) uf2[j] = 2.f * __ldg(upf + j);
            const int q = TILE + tid;
            float xh[7];
            #pragma unroll
            for (int j = 0; j < 7; j++) {
                int g = m0 + q - 6 + j;
                xh[j] = xrow[g > TLEN - 1 ? TLEN - 1 : g];
            }
            float ue =      uf2[11] * xh[0];
            ue = fmaf(uf2[9],  xh[1], ue);
            ue = fmaf(uf2[7],  xh[2], ue);
            ue = fmaf(uf2[5],  xh[3], ue);
            ue = fmaf(uf2[3],  xh[4], ue);
            ue = fmaf(uf2[1],  xh[5], ue);
            float uo =      uf2[10] * xh[1];
            uo = fmaf(uf2[8],  xh[2], uo);
            uo = fmaf(uf2[6],  xh[3], uo);
            uo = fmaf(uf2[4],  xh[4], uo);
            uo = fmaf(uf2[2],  xh[5], uo);
            uo = fmaf(uf2[0],  xh[6], uo);
            float Eh = snake(ue, a, ib);
            float Oh = snake(uo, a, ib);
            if (last) {
                // t > 16383 clamps to act[16383] == O[1026]
                if (tid == 2) {
                    Es[q] = Eh; Os[q] = Oh;
                    Es[1027] = Oh; Es[1028] = Oh; Es[1029] = Oh;
                    Os[1027] = Oh; Os[1028] = Oh; Os[1029] = Oh;
                } else if (tid < 2) {
                    Es[q] = Eh; Os[q] = Oh;
                }
            } else {
                Es[q] = Eh; Os[q] = Oh;
            }
        }
    }
    __syncthreads();

    // ---- phase 2: out[m0+b+k] = sum_r df[2r]*O[b+k+r] + df[2r+1]*E[b+k+r+1] ----
    {
        float o[9], e[10];
        o[0] = ov[0]; o[1] = ov[1]; o[2] = ov[2]; o[3] = ov[3];
        e[1] = ev[1]; e[2] = ev[2]; e[3] = ev[3];
        float4 o4 = *(const float4*)(Os + b + 4);
        o[4] = o4.x; o[5] = o4.y; o[6] = o4.z; o[7] = o4.w;
        o[8] = Os[b + 8];
        float4 e4 = *(const float4*)(Es + b + 4);
        e[4] = e4.x; e[5] = e4.y; e[6] = e4.z; e[7] = e4.w;
        float2 e89 = *(const float2*)(Es + b + 8);
        e[8] = e89.x; e[9] = e89.y;

        u64 Fd[6];
        {
            const float4* d4 = (const float4*)dnf;
            float4 d0 = __ldg(d4), d1 = __ldg(d4 + 1), d2 = __ldg(d4 + 2);
            Fd[0] = pk2(d0.x, d0.y);
            Fd[1] = pk2(d0.z, d0.w);
            Fd[2] = pk2(d1.x, d1.y);
            Fd[3] = pk2(d1.z, d1.w);
            Fd[4] = pk2(d2.x, d2.y);
            Fd[5] = pk2(d2.z, d2.w);
        }
        u64 Pa[9];                         // Pa[i] = (o[i], e[i+1])
        #pragma unroll
        for (int i = 0; i < 9; i++) Pa[i] = pk2(o[i], e[i + 1]);

        float4 r4;
        #pragma unroll
        for (int k = 0; k < 4; k++) {
            u64 acc = mul2(Fd[0], Pa[k]);
            acc = fma2(Fd[1], Pa[k + 1], acc);
            acc = fma2(Fd[2], Pa[k + 2], acc);
            acc = fma2(Fd[3], Pa[k + 3], acc);
            acc = fma2(Fd[4], Pa[k + 4], acc);
            acc = fma2(Fd[5], Pa[k + 5], acc);
            float lo, hi; upk2(acc, lo, hi);
            ((float*)&r4)[k] = lo + hi;
        }
        *(float4*)(out + (size_t)row * TLEN + m0 + b) = r4;
    }
}

extern "C" void kernel_launch(void* const* d_in, const int* in_sizes, int n_in,
                              void* d_out, int out_size) {
    const float* x     = (const float*)d_in[0];
    const float* upf   = (const float*)d_in[1];
    const float* dnf   = (const float*)d_in[2];
    const float* alpha = (const float*)d_in[3];
    const float* beta  = (const float*)d_in[4];
    float* out = (float*)d_out;

    const int rows = in_sizes[0] / TLEN;   // B*C
    const int nch  = in_sizes[3];          // C

    dim3 grid(TLEN / TILE, rows);
    act1d_kernel<<<grid, NTHR>>>(x, upf, dnf, alpha, beta, out, nch);
}

// round 4
// speedup vs baseline: 1.8451x; 1.1572x over previous
#include <cuda_runtime.h>

#define TLEN 8192
#define TILE 1024
#define NTHR 256
#define NEO  1032            // 1030 act pairs used + float4 pad

// snake(u) = u + ib*sin^2(a*u) = (u + c0) - c0*cos(2a*u),  c0 = ib/2
__device__ __forceinline__ float snake(float u, float a2, float c0) {
    return fmaf(-c0, __cosf(u * a2), u + c0);
}

__global__ void __launch_bounds__(NTHR, 6)
act1d_kernel(const float* __restrict__ x,
             const float* __restrict__ upf,
             const float* __restrict__ dnf,
             const float* __restrict__ alpha,
             const float* __restrict__ beta,
             float* __restrict__ out,
             int nch)
{
    __shared__ __align__(16) float Es[NEO];
    __shared__ __align__(16) float Os[NEO];

    const int tid = threadIdx.x;
    const int row = blockIdx.y;
    const int m0  = blockIdx.x * TILE;
    const int ch  = row % nch;
    const int b   = 4 * tid;                     // first owned pair / output

    const float a2 = 2.0f * __expf(__ldg(alpha + ch));
    const float c0 = 0.5f * __fdividef(1.0f, __expf(__ldg(beta + ch)) + 1e-9f);

    const float* xrow = x + (size_t)row * TLEN;
    const bool first = (m0 == 0);
    const bool last  = (m0 + TILE == TLEN);

    // ---- x values for owned pairs: xv[j] = x_clamped[m0 + b - 8 + j] ----
    float xv[12];
    if (!(first && tid < 32)) {                  // warp-uniform branch
        const float4* s = (const float4*)(xrow + (m0 + b - 8));
        float4 v0 = s[0], v1 = s[1], v2 = s[2];
        xv[0]=v0.x; xv[1]=v0.y; xv[2] =v0.z; xv[3] =v0.w;
        xv[4]=v1.x; xv[5]=v1.y; xv[6] =v1.z; xv[7] =v1.w;
        xv[8]=v2.x; xv[9]=v2.y; xv[10]=v2.z; xv[11]=v2.w;
    } else {                                     // first block, warp 0: clamp low
        const int xb = b - 8;
        #pragma unroll
        for (int j = 0; j < 12; j++) {
            int g = xb + j;
            xv[j] = xrow[g < 0 ? 0 : g];
        }
    }

    // ---- phase 1: 4 (E,O) act pairs, scalar FMA ----
    // pair q=b+k:  E[q]=snake(sum_r 2uf[11-2r]*xv[k+2+r]),  O[q]=snake(sum_r 2uf[10-2r]*xv[k+3+r])
    float ev[4], ov[4];
    {
        float uf2[12];
        {
            const float4* u4 = (const float4*)upf;
            float4 u0 = __ldg(u4), u1 = __ldg(u4 + 1), u2 = __ldg(u4 + 2);
            uf2[0] = 2.f*u0.x; uf2[1] = 2.f*u0.y; uf2[2]  = 2.f*u0.z; uf2[3]  = 2.f*u0.w;
            uf2[4] = 2.f*u1.x; uf2[5] = 2.f*u1.y; uf2[6]  = 2.f*u1.z; uf2[7]  = 2.f*u1.w;
            uf2[8] = 2.f*u2.x; uf2[9] = 2.f*u2.y; uf2[10] = 2.f*u2.z; uf2[11] = 2.f*u2.w;
        }

        #pragma unroll
        for (int k = 0; k < 4; k++) {
            float ue =      uf2[11] * xv[k + 2];
            ue = fmaf(uf2[9],  xv[k + 3], ue);
            ue = fmaf(uf2[7],  xv[k + 4], ue);
            ue = fmaf(uf2[5],  xv[k + 5], ue);
            ue = fmaf(uf2[3],  xv[k + 6], ue);
            ue = fmaf(uf2[1],  xv[k + 7], ue);
            float uo =      uf2[10] * xv[k + 3];
            uo = fmaf(uf2[8],  xv[k + 4], uo);
            uo = fmaf(uf2[6],  xv[k + 5], uo);
            uo = fmaf(uf2[4],  xv[k + 6], uo);
            uo = fmaf(uf2[2],  xv[k + 7], uo);
            uo = fmaf(uf2[0],  xv[k + 8], uo);
            ev[k] = snake(ue, a2, c0);
            ov[k] = snake(uo, a2, c0);
        }

        // first block, tid 0: act indices t<0 clamp to act[0] == E[3]
        if (first && tid == 0) {
            ev[0] = ev[1] = ev[2] = ev[3];
            ov[0] = ov[1] = ov[2] = ev[3];
        }

        *(float4*)(Es + b) = make_float4(ev[0], ev[1], ev[2], ev[3]);
        *(float4*)(Os + b) = make_float4(ov[0], ov[1], ov[2], ov[3]);

        // halo pairs q = 1024..1029 (scalar, clamped global reads)
        if (tid < 6) {
            const int q = TILE + tid;
            float xh[7];
            #pragma unroll
            for (int j = 0; j < 7; j++) {
                int g = m0 + q - 6 + j;
                xh[j] = xrow[g > TLEN - 1 ? TLEN - 1 : g];
            }
            float ue =      uf2[11] * xh[0];
            ue = fmaf(uf2[9],  xh[1], ue);
            ue = fmaf(uf2[7],  xh[2], ue);
            ue = fmaf(uf2[5],  xh[3], ue);
            ue = fmaf(uf2[3],  xh[4], ue);
            ue = fmaf(uf2[1],  xh[5], ue);
            float uo =      uf2[10] * xh[1];
            uo = fmaf(uf2[8],  xh[2], uo);
            uo = fmaf(uf2[6],  xh[3], uo);
            uo = fmaf(uf2[4],  xh[4], uo);
            uo = fmaf(uf2[2],  xh[5], uo);
            uo = fmaf(uf2[0],  xh[6], uo);
            float Eh = snake(ue, a2, c0);
            float Oh = snake(uo, a2, c0);
            if (last) {
                // t > 16383 clamps to act[16383] == O[1026]
                if (tid == 2) {
                    Es[q] = Eh; Os[q] = Oh;
                    Es[1027] = Oh; Es[1028] = Oh; Es[1029] = Oh;
                    Os[1027] = Oh; Os[1028] = Oh; Os[1029] = Oh;
                } else if (tid < 2) {
                    Es[q] = Eh; Os[q] = Oh;
                }
            } else {
                Es[q] = Eh; Os[q] = Oh;
            }
        }
    }
    __syncthreads();

    // ---- phase 2: out[m0+b+k] = sum_r df[2r]*O[b+k+r] + df[2r+1]*E[b+k+r+1] ----
    {
        float df[12];
        {
            const float4* d4 = (const float4*)dnf;
            float4 d0 = __ldg(d4), d1 = __ldg(d4 + 1), d2 = __ldg(d4 + 2);
            df[0] = d0.x; df[1] = d0.y; df[2]  = d0.z; df[3]  = d0.w;
            df[4] = d1.x; df[5] = d1.y; df[6]  = d1.z; df[7]  = d1.w;
            df[8] = d2.x; df[9] = d2.y; df[10] = d2.z; df[11] = d2.w;
        }

        float o[9], e[10];
        o[0] = ov[0]; o[1] = ov[1]; o[2] = ov[2]; o[3] = ov[3];
        e[1] = ev[1]; e[2] = ev[2]; e[3] = ev[3];
        float4 o4 = *(const float4*)(Os + b + 4);
        o[4] = o4.x; o[5] = o4.y; o[6] = o4.z; o[7] = o4.w;
        o[8] = Os[b + 8];
        float4 e4 = *(const float4*)(Es + b + 4);
        e[4] = e4.x; e[5] = e4.y; e[6] = e4.z; e[7] = e4.w;
        float2 e89 = *(const float2*)(Es + b + 8);
        e[8] = e89.x; e[9] = e89.y;

        float4 r4;
        #pragma unroll
        for (int k = 0; k < 4; k++) {
            float r = df[0] * o[k];
            r = fmaf(df[1],  e[k + 1], r);
            r = fmaf(df[2],  o[k + 1], r);
            r = fmaf(df[3],  e[k + 2], r);
            r = fmaf(df[4],  o[k + 2], r);
            r = fmaf(df[5],  e[k + 3], r);
            r = fmaf(df[6],  o[k + 3], r);
            r = fmaf(df[7],  e[k + 4], r);
            r = fmaf(df[8],  o[k + 4], r);
            r = fmaf(df[9],  e[k + 5], r);
            r = fmaf(df[10], o[k + 5], r);
            r = fmaf(df[11], e[k + 6], r);
            ((float*)&r4)[k] = r;
        }
        *(float4*)(out + (size_t)row * TLEN + m0 + b) = r4;
    }
}

extern "C" void kernel_launch(void* const* d_in, const int* in_sizes, int n_in,
                              void* d_out, int out_size) {
    const float* x     = (const float*)d_in[0];
    const float* upf   = (const float*)d_in[1];
    const float* dnf   = (const float*)d_in[2];
    const float* alpha = (const float*)d_in[3];
    const float* beta  = (const float*)d_in[4];
    float* out = (float*)d_out;

    const int rows = in_sizes[0] / TLEN;   // B*C
    const int nch  = in_sizes[3];          // C

    dim3 grid(TLEN / TILE, rows);
    act1d_kernel<<<grid, NTHR>>>(x, upf, dnf, alpha, beta, out, nch);
}